// round 3
// baseline (speedup 1.0000x reference)
#include <cuda_runtime.h>

// ---------------- problem constants ----------------
#define BQ 8
#define DIMC 256
#define CDIMC 512
#define TT 8192
#define NH 8
#define DH 32
#define MLPD 640
#define EPSV 1e-5f

// ---------------- scratch (device globals; no allocation allowed) ----------------
__device__ float g_big [(size_t)BQ * 768 * TT];   // qkv(768) / ckv(512) / mlp-h(640) / o2(256)
__device__ float g_attn[(size_t)BQ * DIMC * TT];  // attn out / q2
__device__ float g_so  [(size_t)BQ * DIMC * TT];  // pre-norm conv outputs
__device__ float g_x   [(size_t)BQ * DIMC * TT];  // running residual x
__device__ float g_wt  [(size_t)BQ * 512 * 512];  // folded transposed weights (max M*K=262144)
__device__ float g_beff[BQ * 1024];
__device__ float g_mu  [BQ * 32];
__device__ float g_rs  [BQ * 32];
__device__ float g_affa[BQ * CDIMC];
__device__ float g_affb[BQ * CDIMC];
__device__ float g_kmax[BQ * 256];
__device__ float g_kinv[BQ * 256];
__device__ float g_ctx [BQ * NH * DH * DH];       // 65536
__device__ float g_ctxp[8 * BQ * NH * DH * DH];   // per-slice partials (deterministic reduce)

// ---------------- group-norm statistics ----------------
// grid = B*32 groups; each group is a CONTIGUOUS chunk of GC*T floats.
__global__ void gn_stats_kernel(const float* __restrict__ x, int GC,
                                float* __restrict__ mu, float* __restrict__ rs)
{
    const size_t n = (size_t)GC * TT;
    const float4* x4 = (const float4*)(x + (size_t)blockIdx.x * n);
    const int n4 = (int)(n >> 2);
    float s = 0.f, sq = 0.f;
    for (int i = threadIdx.x; i < n4; i += 256) {
        float4 v = x4[i];
        s  += (v.x + v.y) + (v.z + v.w);
        sq += v.x*v.x + v.y*v.y + v.z*v.z + v.w*v.w;
    }
    __shared__ float sh1[8], sh2[8];
    int lane = threadIdx.x & 31, w = threadIdx.x >> 5;
    #pragma unroll
    for (int o = 16; o > 0; o >>= 1) {
        s  += __shfl_xor_sync(0xffffffffu, s, o);
        sq += __shfl_xor_sync(0xffffffffu, sq, o);
    }
    if (lane == 0) { sh1[w] = s; sh2[w] = sq; }
    __syncthreads();
    if (threadIdx.x < 8) {
        s = sh1[threadIdx.x]; sq = sh2[threadIdx.x];
        #pragma unroll
        for (int o = 4; o > 0; o >>= 1) {
            s  += __shfl_xor_sync(0xffu, s, o);
            sq += __shfl_xor_sync(0xffu, sq, o);
        }
        if (threadIdx.x == 0) {
            float inv_n = 1.f / (float)n;
            float m = s * inv_n;
            float var = sq * inv_n - m * m;
            mu[blockIdx.x] = m;
            rs[blockIdx.x] = rsqrtf(fmaxf(var, 0.f) + EPSV);
        }
    }
}

// per-channel affine so gn(x) == a[c]*x + bb[c]
__global__ void affine_kernel(const float* __restrict__ g, const float* __restrict__ be,
                              const float* __restrict__ mu, const float* __restrict__ rs,
                              float* __restrict__ a, float* __restrict__ bb, int C)
{
    int b = blockIdx.x;
    int GC = C >> 5;
    for (int c = threadIdx.x; c < C; c += blockDim.x) {
        int grp = c / GC;
        float r = rs[b*32 + grp], m = mu[b*32 + grp];
        float av = g[c] * r;
        a [b*C + c] = av;
        bb[b*C + c] = be[c] - m * av;
    }
}

// ---------------- weight fold: Wt[b][k][m] = W[m][k] * a[b][k] ----------------
__global__ void foldT_kernel(const float* __restrict__ W, const float* __restrict__ a,
                             float* __restrict__ Wt, int M, int K)
{
    __shared__ float tile[32][33];
    int k0 = blockIdx.x * 32, m0 = blockIdx.y * 32, b = blockIdx.z;
    for (int i = threadIdx.y; i < 32; i += 8)
        tile[i][threadIdx.x] = W[(size_t)(m0 + i) * K + k0 + threadIdx.x];
    __syncthreads();
    float* Wo = Wt + (size_t)b * M * K;
    for (int i = threadIdx.y; i < 32; i += 8) {
        int k = k0 + i;
        float av = a ? a[b*K + k] : 1.f;
        Wo[(size_t)k * M + m0 + threadIdx.x] = tile[threadIdx.x][i] * av;
    }
}

// beff[b][m] = sum_k W[m][k]*bb[b][k] + bias[m]
__global__ void beff_kernel(const float* __restrict__ W, const float* __restrict__ bbv,
                            const float* __restrict__ bias, float* __restrict__ beff,
                            int M, int K)
{
    int m = blockIdx.x, b = blockIdx.y;
    float s = 0.f;
    for (int k = threadIdx.x; k < K; k += 128)
        s += W[(size_t)m*K + k] * bbv[b*K + k];
    __shared__ float sh[4];
    int lane = threadIdx.x & 31, w = threadIdx.x >> 5;
    #pragma unroll
    for (int o = 16; o > 0; o >>= 1) s += __shfl_xor_sync(0xffffffffu, s, o);
    if (lane == 0) sh[w] = s;
    __syncthreads();
    if (threadIdx.x == 0)
        beff[(size_t)b*M + m] = sh[0] + sh[1] + sh[2] + sh[3] + (bias ? bias[m] : 0.f);
}

// ---------------- SGEMM:  Y[b][m][n] = sum_k Wt[b][k][m] * X[b][k][n] + beff[b][m] ----------------
// BM=BN=128, BK=16, 256 threads, 8x8 per thread (4x4 quads at +0/+64).
__global__ __launch_bounds__(256, 2)
void gemm_kernel(const float* __restrict__ Wt, size_t wStrideB,
                 const float* __restrict__ beff, int beffStride,
                 const float* __restrict__ X, size_t xStrideB,
                 float* __restrict__ Y, size_t yStrideB,
                 const float* __restrict__ R, size_t rStrideB,
                 int M, int K, int ep)
{
    __shared__ float Ws[16][128];
    __shared__ float Xs[16][128];
    const int b = blockIdx.z;
    const int n0 = blockIdx.x * 128;
    const int m0 = blockIdx.y * 128;
    const float* Wb = Wt + (size_t)b * wStrideB;
    const float* Xb = X  + (size_t)b * xStrideB;
    float acc[8][8];
    #pragma unroll
    for (int i = 0; i < 8; i++)
        #pragma unroll
        for (int j = 0; j < 8; j++) acc[i][j] = 0.f;

    const int tid = threadIdx.x;
    const int tx = tid & 15, ty = tid >> 4;

    for (int k0 = 0; k0 < K; k0 += 16) {
        #pragma unroll
        for (int u = 0; u < 2; u++) {
            int f = tid + u * 256;         // 512 float4 per tile
            int k = f >> 5, c4 = f & 31;
            ((float4*)Ws[k])[c4] = ((const float4*)(Wb + (size_t)(k0 + k) * M + m0))[c4];
            ((float4*)Xs[k])[c4] = ((const float4*)(Xb + (size_t)(k0 + k) * TT + n0))[c4];
        }
        __syncthreads();
        #pragma unroll
        for (int k = 0; k < 16; k++) {
            float ar[8], br[8];
            *(float4*)&ar[0] = *(const float4*)&Ws[k][ty * 4];
            *(float4*)&ar[4] = *(const float4*)&Ws[k][64 + ty * 4];
            *(float4*)&br[0] = *(const float4*)&Xs[k][tx * 4];
            *(float4*)&br[4] = *(const float4*)&Xs[k][64 + tx * 4];
            #pragma unroll
            for (int i = 0; i < 8; i++)
                #pragma unroll
                for (int j = 0; j < 8; j++)
                    acc[i][j] += ar[i] * br[j];
        }
        __syncthreads();
    }

    #pragma unroll
    for (int i = 0; i < 8; i++) {
        int m = m0 + ty * 4 + (i & 3) + ((i >> 2) << 6);
        float bv = beff[(size_t)b * beffStride + m];
        #pragma unroll
        for (int jh = 0; jh < 2; jh++) {
            int n = n0 + tx * 4 + (jh << 6);
            float4 v;
            v.x = acc[i][jh*4+0] + bv;
            v.y = acc[i][jh*4+1] + bv;
            v.z = acc[i][jh*4+2] + bv;
            v.w = acc[i][jh*4+3] + bv;
            if (ep == 1) {                       // SiLU
                v.x = v.x / (1.f + expf(-v.x));
                v.y = v.y / (1.f + expf(-v.y));
                v.z = v.z / (1.f + expf(-v.z));
                v.w = v.w / (1.f + expf(-v.w));
            } else if (ep == 2) {                // + residual
                float4 rv = *(const float4*)(R + (size_t)b * rStrideB + (size_t)m * TT + n);
                v.x += rv.x; v.y += rv.y; v.z += rv.z; v.w += rv.w;
            }
            *(float4*)(Y + (size_t)b * yStrideB + (size_t)m * TT + n) = v;
        }
    }
}

// ---------------- k softmax row stats (max + 1/sum over T) ----------------
__global__ void ksm_stats_kernel(const float* __restrict__ kbase, size_t strideB,
                                 float* __restrict__ kmax, float* __restrict__ kinv)
{
    int r = blockIdx.x, b = blockIdx.y;
    const float4* p4 = (const float4*)(kbase + (size_t)b * strideB + (size_t)r * TT);
    float mx = -1e30f;
    for (int i = threadIdx.x; i < TT/4; i += 256) {
        float4 v = p4[i];
        mx = fmaxf(mx, fmaxf(fmaxf(v.x, v.y), fmaxf(v.z, v.w)));
    }
    __shared__ float sh[8];
    __shared__ float bmax, bsum;
    int lane = threadIdx.x & 31, w = threadIdx.x >> 5;
    #pragma unroll
    for (int o = 16; o > 0; o >>= 1) mx = fmaxf(mx, __shfl_xor_sync(0xffffffffu, mx, o));
    if (lane == 0) sh[w] = mx;
    __syncthreads();
    if (threadIdx.x < 8) {
        mx = sh[threadIdx.x];
        #pragma unroll
        for (int o = 4; o > 0; o >>= 1) mx = fmaxf(mx, __shfl_xor_sync(0xffu, mx, o));
        if (threadIdx.x == 0) bmax = mx;
    }
    __syncthreads();
    float m = bmax;
    float s = 0.f;
    for (int i = threadIdx.x; i < TT/4; i += 256) {
        float4 v = p4[i];
        s += expf(v.x - m) + expf(v.y - m) + expf(v.z - m) + expf(v.w - m);
    }
    #pragma unroll
    for (int o = 16; o > 0; o >>= 1) s += __shfl_xor_sync(0xffffffffu, s, o);
    if (lane == 0) sh[w] = s;
    __syncthreads();
    if (threadIdx.x < 8) {
        s = sh[threadIdx.x];
        #pragma unroll
        for (int o = 4; o > 0; o >>= 1) s += __shfl_xor_sync(0xffu, s, o);
        if (threadIdx.x == 0) bsum = s;
    }
    __syncthreads();
    if (threadIdx.x == 0) {
        kmax[b*256 + r] = m;
        kinv[b*256 + r] = 1.f / bsum;
    }
}

// ---------------- ctx partials: ctx[b,h,d,e] += sum_t ksm[d,t]*v[e,t] over one t-slice ----------------
__global__ void ctx_kernel(const float* __restrict__ kv, size_t strideB, int koff, int voff,
                           const float* __restrict__ kmax, const float* __restrict__ kinv,
                           float* __restrict__ cpart)
{
    int bh = blockIdx.x;             // 0..63
    int slice = blockIdx.y;          // 0..7
    int b = bh / NH, h = bh % NH;
    __shared__ float ks[32][65], vs[32][65];
    __shared__ float km[32], ki[32];
    int tid = threadIdx.x;
    if (tid < 32) {
        km[tid] = kmax[b*256 + h*32 + tid];
        ki[tid] = kinv[b*256 + h*32 + tid];
    }
    const float* kp = kv + (size_t)b*strideB + (size_t)(koff + h*32)*TT + slice*1024;
    const float* vp = kv + (size_t)b*strideB + (size_t)(voff + h*32)*TT + slice*1024;
    int d = tid >> 3, e0 = (tid & 7) * 4;
    float c0 = 0.f, c1 = 0.f, c2 = 0.f, c3 = 0.f;
    for (int tc = 0; tc < 1024; tc += 64) {
        __syncthreads();
        for (int i = tid; i < 32*64; i += 256) {
            int r = i >> 6, t = i & 63;
            ks[r][t] = expf(kp[(size_t)r*TT + tc + t] - km[r]) * ki[r];
            vs[r][t] = vp[(size_t)r*TT + tc + t];
        }
        __syncthreads();
        #pragma unroll 8
        for (int t = 0; t < 64; t++) {
            float kd = ks[d][t];
            c0 += kd * vs[e0+0][t];
            c1 += kd * vs[e0+1][t];
            c2 += kd * vs[e0+2][t];
            c3 += kd * vs[e0+3][t];
        }
    }
    float* cp = cpart + (size_t)slice*65536 + (size_t)bh*1024 + d*32 + e0;
    cp[0] = c0; cp[1] = c1; cp[2] = c2; cp[3] = c3;
}

__global__ void ctx_reduce_kernel(const float* __restrict__ cpart, float* __restrict__ ctx)
{
    int i = blockIdx.x * 256 + threadIdx.x;   // 65536 total
    float s = 0.f;
    #pragma unroll
    for (int sl = 0; sl < 8; sl++) s += cpart[(size_t)sl*65536 + i];
    ctx[i] = s;
}

// ---------------- attn out: o[e,t] = sum_d ctx[d,e] * softmax_d(q[:,t]) * scale ----------------
__global__ void attn_out_kernel(const float* __restrict__ q, size_t strideB, int qoff,
                                const float* __restrict__ ctx,
                                float* __restrict__ o, size_t oStrideB)
{
    int bh = blockIdx.x;
    int b = bh / NH, h = bh % NH;
    int t = blockIdx.y * 256 + threadIdx.x;
    __shared__ float cs[32][32];
    for (int i = threadIdx.x; i < 1024; i += 256)
        cs[i >> 5][i & 31] = ctx[(size_t)bh*1024 + i];
    __syncthreads();
    const float* qp = q + (size_t)b*strideB + (size_t)(qoff + h*32)*TT + t;
    float p[32];
    float mx = -1e30f;
    #pragma unroll
    for (int d = 0; d < 32; d++) { p[d] = qp[(size_t)d*TT]; mx = fmaxf(mx, p[d]); }
    float s = 0.f;
    #pragma unroll
    for (int d = 0; d < 32; d++) { p[d] = expf(p[d] - mx); s += p[d]; }
    float inv = 0.17677669529663687f / s;   // (1/sqrt(32)) / sum
    #pragma unroll
    for (int d = 0; d < 32; d++) p[d] *= inv;
    float accv[32];
    #pragma unroll
    for (int e = 0; e < 32; e++) accv[e] = 0.f;
    #pragma unroll
    for (int d = 0; d < 32; d++) {
        float pd = p[d];
        #pragma unroll
        for (int e4 = 0; e4 < 8; e4++) {
            float4 cv = *(const float4*)&cs[d][e4*4];
            accv[e4*4+0] += cv.x * pd;
            accv[e4*4+1] += cv.y * pd;
            accv[e4*4+2] += cv.z * pd;
            accv[e4*4+3] += cv.w * pd;
        }
    }
    float* op = o + (size_t)b*oStrideB + (size_t)(h*32)*TT + t;
    #pragma unroll
    for (int e = 0; e < 32; e++) op[(size_t)e*TT] = accv[e];
}

// ---------------- y = gn(v)*g + b + r  (elementwise, float4) ----------------
__global__ void gn_add_kernel(const float* __restrict__ v,
                              const float* __restrict__ gamma, const float* __restrict__ beta,
                              const float* __restrict__ mu, const float* __restrict__ rs,
                              const float* __restrict__ r, float* __restrict__ y)
{
    size_t i = ((size_t)blockIdx.x * 256 + threadIdx.x) * 4;
    int c = (int)((i / TT) % DIMC);
    int b = (int)(i / ((size_t)DIMC * TT));
    int grp = c >> 3;  // GC = 8
    float rr = rs[b*32 + grp], m = mu[b*32 + grp];
    float sc = gamma[c] * rr;
    float sh = beta[c] - m * sc;
    float4 vv = *(const float4*)(v + i);
    float4 rv = *(const float4*)(r + i);
    float4 o;
    o.x = vv.x * sc + sh + rv.x;
    o.y = vv.y * sc + sh + rv.y;
    o.z = vv.z * sc + sh + rv.z;
    o.w = vv.w * sc + sh + rv.w;
    *(float4*)(y + i) = o;
}

// ---------------- host orchestration ----------------
extern "C" void kernel_launch(void* const* d_in, const int* in_sizes, int n_in,
                              void* d_out, int out_size)
{
    const float* x     = (const float*)d_in[0];
    const float* c     = (const float*)d_in[1];
    const float* W_qkv = (const float*)d_in[2];
    const float* W_so  = (const float*)d_in[3];
    const float* b_so  = (const float*)d_in[4];
    const float* sa_g  = (const float*)d_in[5];
    const float* sa_b  = (const float*)d_in[6];
    const float* W_cq  = (const float*)d_in[7];
    const float* W_ckv = (const float*)d_in[8];
    const float* W_co  = (const float*)d_in[9];
    const float* b_co  = (const float*)d_in[10];
    const float* ca_g  = (const float*)d_in[11];
    const float* ca_b  = (const float*)d_in[12];
    const float* W_m1  = (const float*)d_in[13];
    const float* b_m1  = (const float*)d_in[14];
    const float* W_m2  = (const float*)d_in[15];
    const float* b_m2  = (const float*)d_in[16];
    const float* nm_g  = (const float*)d_in[17];
    const float* nm_b  = (const float*)d_in[18];
    const float* nm1_g = (const float*)d_in[19];
    const float* nm1_b = (const float*)d_in[20];
    const float* nm2_g = (const float*)d_in[21];
    const float* nm2_b = (const float*)d_in[22];
    const float* nm3_g = (const float*)d_in[23];
    const float* nm3_b = (const float*)d_in[24];
    float* out = (float*)d_out;

    float *big, *attn, *so, *xb, *wt, *beff, *mu, *rs, *aa, *ab, *kmax, *kinv, *ctx, *ctxp;
    cudaGetSymbolAddress((void**)&big,  g_big);
    cudaGetSymbolAddress((void**)&attn, g_attn);
    cudaGetSymbolAddress((void**)&so,   g_so);
    cudaGetSymbolAddress((void**)&xb,   g_x);
    cudaGetSymbolAddress((void**)&wt,   g_wt);
    cudaGetSymbolAddress((void**)&beff, g_beff);
    cudaGetSymbolAddress((void**)&mu,   g_mu);
    cudaGetSymbolAddress((void**)&rs,   g_rs);
    cudaGetSymbolAddress((void**)&aa,   g_affa);
    cudaGetSymbolAddress((void**)&ab,   g_affb);
    cudaGetSymbolAddress((void**)&kmax, g_kmax);
    cudaGetSymbolAddress((void**)&kinv, g_kinv);
    cudaGetSymbolAddress((void**)&ctx,  g_ctx);
    cudaGetSymbolAddress((void**)&ctxp, g_ctxp);

    const dim3 tb8(32, 8);
    const size_t XT = (size_t)DIMC * TT;   // 256*T

    // ================= Phase 1: self linear attention =================
    gn_stats_kernel<<<BQ*32, 256>>>(x, 8, mu, rs);
    affine_kernel<<<BQ, 256>>>(nm_g, nm_b, mu, rs, aa, ab, 256);
    foldT_kernel<<<dim3(8, 24, BQ), tb8>>>(W_qkv, aa, wt, 768, 256);
    beff_kernel<<<dim3(768, BQ), 128>>>(W_qkv, ab, nullptr, beff, 768, 256);
    gemm_kernel<<<dim3(64, 6, BQ), 256>>>(wt, (size_t)768*256, beff, 768,
                                          x, XT, big, (size_t)768*TT,
                                          nullptr, 0, 768, 256, 0);
    ksm_stats_kernel<<<dim3(256, BQ), 256>>>(big + (size_t)256*TT, (size_t)768*TT, kmax, kinv);
    ctx_kernel<<<dim3(64, 8), 256>>>(big, (size_t)768*TT, 256, 512, kmax, kinv, ctxp);
    ctx_reduce_kernel<<<256, 256>>>(ctxp, ctx);
    attn_out_kernel<<<dim3(64, 32), 256>>>(big, (size_t)768*TT, 0, ctx, attn, XT);
    foldT_kernel<<<dim3(8, 8, 1), tb8>>>(W_so, nullptr, wt, 256, 256);
    gemm_kernel<<<dim3(64, 2, BQ), 256>>>(wt, 0, b_so, 0,
                                          attn, XT, so, XT,
                                          nullptr, 0, 256, 256, 0);
    gn_stats_kernel<<<BQ*32, 256>>>(so, 8, mu, rs);
    gn_add_kernel<<<16384, 256>>>(so, sa_g, sa_b, mu, rs, x, xb);

    // ================= Phase 2: cross linear attention =================
    gn_stats_kernel<<<BQ*32, 256>>>(xb, 8, mu, rs);
    affine_kernel<<<BQ, 256>>>(nm1_g, nm1_b, mu, rs, aa, ab, 256);
    foldT_kernel<<<dim3(8, 8, BQ), tb8>>>(W_cq, aa, wt, 256, 256);
    beff_kernel<<<dim3(256, BQ), 128>>>(W_cq, ab, nullptr, beff, 256, 256);
    gemm_kernel<<<dim3(64, 2, BQ), 256>>>(wt, (size_t)256*256, beff, 256,
                                          xb, XT, attn, XT,
                                          nullptr, 0, 256, 256, 0);
    gn_stats_kernel<<<BQ*32, 256>>>(c, 16, mu, rs);
    affine_kernel<<<BQ, 256>>>(nm3_g, nm3_b, mu, rs, aa, ab, 512);
    foldT_kernel<<<dim3(16, 16, BQ), tb8>>>(W_ckv, aa, wt, 512, 512);
    beff_kernel<<<dim3(512, BQ), 128>>>(W_ckv, ab, nullptr, beff, 512, 512);
    gemm_kernel<<<dim3(64, 4, BQ), 256>>>(wt, (size_t)512*512, beff, 512,
                                          c, (size_t)512*TT, big, (size_t)512*TT,
                                          nullptr, 0, 512, 512, 0);
    ksm_stats_kernel<<<dim3(256, BQ), 256>>>(big, (size_t)512*TT, kmax, kinv);
    ctx_kernel<<<dim3(64, 8), 256>>>(big, (size_t)512*TT, 0, 256, kmax, kinv, ctxp);
    ctx_reduce_kernel<<<256, 256>>>(ctxp, ctx);
    attn_out_kernel<<<dim3(64, 32), 256>>>(attn, XT, 0, ctx, big, XT);
    foldT_kernel<<<dim3(8, 8, 1), tb8>>>(W_co, nullptr, wt, 256, 256);
    gemm_kernel<<<dim3(64, 2, BQ), 256>>>(wt, 0, b_co, 0,
                                          big, XT, so, XT,
                                          nullptr, 0, 256, 256, 0);
    gn_stats_kernel<<<BQ*32, 256>>>(so, 8, mu, rs);
    gn_add_kernel<<<16384, 256>>>(so, ca_g, ca_b, mu, rs, xb, xb);

    // ================= Phase 3: SiLU MLP =================
    gn_stats_kernel<<<BQ*32, 256>>>(xb, 8, mu, rs);
    affine_kernel<<<BQ, 256>>>(nm2_g, nm2_b, mu, rs, aa, ab, 256);
    foldT_kernel<<<dim3(8, 20, BQ), tb8>>>(W_m1, aa, wt, 640, 256);
    beff_kernel<<<dim3(640, BQ), 128>>>(W_m1, ab, b_m1, beff, 640, 256);
    gemm_kernel<<<dim3(64, 5, BQ), 256>>>(wt, (size_t)640*256, beff, 640,
                                          xb, XT, big, (size_t)640*TT,
                                          nullptr, 0, 640, 256, 1 /*silu*/);
    foldT_kernel<<<dim3(20, 8, 1), tb8>>>(W_m2, nullptr, wt, 256, 640);
    gemm_kernel<<<dim3(64, 2, BQ), 256>>>(wt, 0, b_m2, 0,
                                          big, (size_t)640*TT, out, XT,
                                          xb, XT, 256, 640, 2 /*residual*/);
}

// round 4
// speedup vs baseline: 1.0011x; 1.0011x over previous
#include <cuda_runtime.h>

// ---------------- problem constants ----------------
#define BQ 8
#define DIMC 256
#define CDIMC 512
#define TT 8192
#define NH 8
#define DH 32
#define MLPD 640
#define EPSV 1e-5f

// ---------------- scratch (device globals; no allocation allowed) ----------------
__device__ float g_big [(size_t)BQ * 768 * TT];   // qkv(768) / ckv(512) / mlp-h(640) / o2(256)
__device__ float g_attn[(size_t)BQ * DIMC * TT];  // attn out / q2
__device__ float g_so  [(size_t)BQ * DIMC * TT];  // pre-norm conv outputs
__device__ float g_x   [(size_t)BQ * DIMC * TT];  // running residual x
__device__ float g_wt  [(size_t)BQ * 512 * 512];  // folded transposed weights (max M*K=262144)
__device__ float g_beff[BQ * 1024];
__device__ float g_mu  [BQ * 32];
__device__ float g_rs  [BQ * 32];
__device__ float g_affa[BQ * CDIMC];
__device__ float g_affb[BQ * CDIMC];
__device__ float g_kmax[BQ * 256];
__device__ float g_kinv[BQ * 256];
__device__ float g_ctx [BQ * NH * DH * DH];       // 65536
__device__ float g_ctxp[8 * BQ * NH * DH * DH];   // per-slice partials (deterministic reduce)

// ---------------- group-norm statistics ----------------
// grid = B*32 groups; each group is a CONTIGUOUS chunk of GC*T floats.
__global__ void gn_stats_kernel(const float* __restrict__ x, int GC,
                                float* __restrict__ mu, float* __restrict__ rs)
{
    const size_t n = (size_t)GC * TT;
    const float4* x4 = (const float4*)(x + (size_t)blockIdx.x * n);
    const int n4 = (int)(n >> 2);
    float s = 0.f, sq = 0.f;
    for (int i = threadIdx.x; i < n4; i += 256) {
        float4 v = x4[i];
        s  += (v.x + v.y) + (v.z + v.w);
        sq += v.x*v.x + v.y*v.y + v.z*v.z + v.w*v.w;
    }
    __shared__ float sh1[8], sh2[8];
    int lane = threadIdx.x & 31, w = threadIdx.x >> 5;
    #pragma unroll
    for (int o = 16; o > 0; o >>= 1) {
        s  += __shfl_xor_sync(0xffffffffu, s, o);
        sq += __shfl_xor_sync(0xffffffffu, sq, o);
    }
    if (lane == 0) { sh1[w] = s; sh2[w] = sq; }
    __syncthreads();
    if (threadIdx.x < 8) {
        s = sh1[threadIdx.x]; sq = sh2[threadIdx.x];
        #pragma unroll
        for (int o = 4; o > 0; o >>= 1) {
            s  += __shfl_xor_sync(0xffu, s, o);
            sq += __shfl_xor_sync(0xffu, sq, o);
        }
        if (threadIdx.x == 0) {
            float inv_n = 1.f / (float)n;
            float m = s * inv_n;
            float var = sq * inv_n - m * m;
            mu[blockIdx.x] = m;
            rs[blockIdx.x] = rsqrtf(fmaxf(var, 0.f) + EPSV);
        }
    }
}

// per-channel affine so gn(x) == a[c]*x + bb[c]
__global__ void affine_kernel(const float* __restrict__ g, const float* __restrict__ be,
                              const float* __restrict__ mu, const float* __restrict__ rs,
                              float* __restrict__ a, float* __restrict__ bb, int C)
{
    int b = blockIdx.x;
    int GC = C >> 5;
    for (int c = threadIdx.x; c < C; c += blockDim.x) {
        int grp = c / GC;
        float r = rs[b*32 + grp], m = mu[b*32 + grp];
        float av = g[c] * r;
        a [b*C + c] = av;
        bb[b*C + c] = be[c] - m * av;
    }
}

// ---------------- weight fold: Wt[b][k][m] = W[m][k] * a[b][k] ----------------
__global__ void foldT_kernel(const float* __restrict__ W, const float* __restrict__ a,
                             float* __restrict__ Wt, int M, int K)
{
    __shared__ float tile[32][33];
    int k0 = blockIdx.x * 32, m0 = blockIdx.y * 32, b = blockIdx.z;
    for (int i = threadIdx.y; i < 32; i += 8)
        tile[i][threadIdx.x] = W[(size_t)(m0 + i) * K + k0 + threadIdx.x];
    __syncthreads();
    float* Wo = Wt + (size_t)b * M * K;
    for (int i = threadIdx.y; i < 32; i += 8) {
        int k = k0 + i;
        float av = a ? a[b*K + k] : 1.f;
        Wo[(size_t)k * M + m0 + threadIdx.x] = tile[threadIdx.x][i] * av;
    }
}

// beff[b][m] = sum_k W[m][k]*bb[b][k] + bias[m]
__global__ void beff_kernel(const float* __restrict__ W, const float* __restrict__ bbv,
                            const float* __restrict__ bias, float* __restrict__ beff,
                            int M, int K)
{
    int m = blockIdx.x, b = blockIdx.y;
    float s = 0.f;
    for (int k = threadIdx.x; k < K; k += 128)
        s += W[(size_t)m*K + k] * bbv[b*K + k];
    __shared__ float sh[4];
    int lane = threadIdx.x & 31, w = threadIdx.x >> 5;
    #pragma unroll
    for (int o = 16; o > 0; o >>= 1) s += __shfl_xor_sync(0xffffffffu, s, o);
    if (lane == 0) sh[w] = s;
    __syncthreads();
    if (threadIdx.x == 0)
        beff[(size_t)b*M + m] = sh[0] + sh[1] + sh[2] + sh[3] + (bias ? bias[m] : 0.f);
}

// ---------------- SGEMM:  Y[b][m][n] = sum_k Wt[b][k][m] * X[b][k][n] + beff[b][m] ----------------
// BM=BN=128, BK=16, 256 threads, 8x8 per thread (4x4 quads at +0/+64).
__global__ __launch_bounds__(256, 2)
void gemm_kernel(const float* __restrict__ Wt, size_t wStrideB,
                 const float* __restrict__ beff, int beffStride,
                 const float* __restrict__ X, size_t xStrideB,
                 float* __restrict__ Y, size_t yStrideB,
                 const float* __restrict__ R, size_t rStrideB,
                 int M, int K, int ep)
{
    __shared__ float Ws[16][128];
    __shared__ float Xs[16][128];
    const int b = blockIdx.z;
    const int n0 = blockIdx.x * 128;
    const int m0 = blockIdx.y * 128;
    const float* Wb = Wt + (size_t)b * wStrideB;
    const float* Xb = X  + (size_t)b * xStrideB;
    float acc[8][8];
    #pragma unroll
    for (int i = 0; i < 8; i++)
        #pragma unroll
        for (int j = 0; j < 8; j++) acc[i][j] = 0.f;

    const int tid = threadIdx.x;
    const int tx = tid & 15, ty = tid >> 4;

    for (int k0 = 0; k0 < K; k0 += 16) {
        #pragma unroll
        for (int u = 0; u < 2; u++) {
            int f = tid + u * 256;         // 512 float4 per tile
            int k = f >> 5, c4 = f & 31;
            ((float4*)Ws[k])[c4] = ((const float4*)(Wb + (size_t)(k0 + k) * M + m0))[c4];
            ((float4*)Xs[k])[c4] = ((const float4*)(Xb + (size_t)(k0 + k) * TT + n0))[c4];
        }
        __syncthreads();
        #pragma unroll
        for (int k = 0; k < 16; k++) {
            float ar[8], br[8];
            *(float4*)&ar[0] = *(const float4*)&Ws[k][ty * 4];
            *(float4*)&ar[4] = *(const float4*)&Ws[k][64 + ty * 4];
            *(float4*)&br[0] = *(const float4*)&Xs[k][tx * 4];
            *(float4*)&br[4] = *(const float4*)&Xs[k][64 + tx * 4];
            #pragma unroll
            for (int i = 0; i < 8; i++)
                #pragma unroll
                for (int j = 0; j < 8; j++)
                    acc[i][j] += ar[i] * br[j];
        }
        __syncthreads();
    }

    #pragma unroll
    for (int i = 0; i < 8; i++) {
        int m = m0 + ty * 4 + (i & 3) + ((i >> 2) << 6);
        float bv = beff[(size_t)b * beffStride + m];
        #pragma unroll
        for (int jh = 0; jh < 2; jh++) {
            int n = n0 + tx * 4 + (jh << 6);
            float4 v;
            v.x = acc[i][jh*4+0] + bv;
            v.y = acc[i][jh*4+1] + bv;
            v.z = acc[i][jh*4+2] + bv;
            v.w = acc[i][jh*4+3] + bv;
            if (ep == 1) {                       // SiLU
                v.x = v.x / (1.f + expf(-v.x));
                v.y = v.y / (1.f + expf(-v.y));
                v.z = v.z / (1.f + expf(-v.z));
                v.w = v.w / (1.f + expf(-v.w));
            } else if (ep == 2) {                // + residual
                float4 rv = *(const float4*)(R + (size_t)b * rStrideB + (size_t)m * TT + n);
                v.x += rv.x; v.y += rv.y; v.z += rv.z; v.w += rv.w;
            }
            *(float4*)(Y + (size_t)b * yStrideB + (size_t)m * TT + n) = v;
        }
    }
}

// ---------------- k softmax row stats (max + 1/sum over T) ----------------
__global__ void ksm_stats_kernel(const float* __restrict__ kbase, size_t strideB,
                                 float* __restrict__ kmax, float* __restrict__ kinv)
{
    int r = blockIdx.x, b = blockIdx.y;
    const float4* p4 = (const float4*)(kbase + (size_t)b * strideB + (size_t)r * TT);
    float mx = -1e30f;
    for (int i = threadIdx.x; i < TT/4; i += 256) {
        float4 v = p4[i];
        mx = fmaxf(mx, fmaxf(fmaxf(v.x, v.y), fmaxf(v.z, v.w)));
    }
    __shared__ float sh[8];
    __shared__ float bmax, bsum;
    int lane = threadIdx.x & 31, w = threadIdx.x >> 5;
    #pragma unroll
    for (int o = 16; o > 0; o >>= 1) mx = fmaxf(mx, __shfl_xor_sync(0xffffffffu, mx, o));
    if (lane == 0) sh[w] = mx;
    __syncthreads();
    if (threadIdx.x < 8) {
        mx = sh[threadIdx.x];
        #pragma unroll
        for (int o = 4; o > 0; o >>= 1) mx = fmaxf(mx, __shfl_xor_sync(0xffu, mx, o));
        if (threadIdx.x == 0) bmax = mx;
    }
    __syncthreads();
    float m = bmax;
    float s = 0.f;
    for (int i = threadIdx.x; i < TT/4; i += 256) {
        float4 v = p4[i];
        s += expf(v.x - m) + expf(v.y - m) + expf(v.z - m) + expf(v.w - m);
    }
    #pragma unroll
    for (int o = 16; o > 0; o >>= 1) s += __shfl_xor_sync(0xffffffffu, s, o);
    if (lane == 0) sh[w] = s;
    __syncthreads();
    if (threadIdx.x < 8) {
        s = sh[threadIdx.x];
        #pragma unroll
        for (int o = 4; o > 0; o >>= 1) s += __shfl_xor_sync(0xffu, s, o);
        if (threadIdx.x == 0) bsum = s;
    }
    __syncthreads();
    if (threadIdx.x == 0) {
        kmax[b*256 + r] = m;
        kinv[b*256 + r] = 1.f / bsum;
    }
}

// ---------------- ctx partials: ctx[b,h,d,e] += sum_t ksm[d,t]*v[e,t] over one t-slice ----------------
__global__ void ctx_kernel(const float* __restrict__ kv, size_t strideB, int koff, int voff,
                           const float* __restrict__ kmax, const float* __restrict__ kinv,
                           float* __restrict__ cpart)
{
    int bh = blockIdx.x;             // 0..63
    int slice = blockIdx.y;          // 0..7
    int b = bh / NH, h = bh % NH;
    __shared__ float ks[32][65], vs[32][65];
    __shared__ float km[32], ki[32];
    int tid = threadIdx.x;
    if (tid < 32) {
        km[tid] = kmax[b*256 + h*32 + tid];
        ki[tid] = kinv[b*256 + h*32 + tid];
    }
    const float* kp = kv + (size_t)b*strideB + (size_t)(koff + h*32)*TT + slice*1024;
    const float* vp = kv + (size_t)b*strideB + (size_t)(voff + h*32)*TT + slice*1024;
    int d = tid >> 3, e0 = (tid & 7) * 4;
    float c0 = 0.f, c1 = 0.f, c2 = 0.f, c3 = 0.f;
    for (int tc = 0; tc < 1024; tc += 64) {
        __syncthreads();
        for (int i = tid; i < 32*64; i += 256) {
            int r = i >> 6, t = i & 63;
            ks[r][t] = expf(kp[(size_t)r*TT + tc + t] - km[r]) * ki[r];
            vs[r][t] = vp[(size_t)r*TT + tc + t];
        }
        __syncthreads();
        #pragma unroll 8
        for (int t = 0; t < 64; t++) {
            float kd = ks[d][t];
            c0 += kd * vs[e0+0][t];
            c1 += kd * vs[e0+1][t];
            c2 += kd * vs[e0+2][t];
            c3 += kd * vs[e0+3][t];
        }
    }
    float* cp = cpart + (size_t)slice*65536 + (size_t)bh*1024 + d*32 + e0;
    cp[0] = c0; cp[1] = c1; cp[2] = c2; cp[3] = c3;
}

__global__ void ctx_reduce_kernel(const float* __restrict__ cpart, float* __restrict__ ctx)
{
    int i = blockIdx.x * 256 + threadIdx.x;   // 65536 total
    float s = 0.f;
    #pragma unroll
    for (int sl = 0; sl < 8; sl++) s += cpart[(size_t)sl*65536 + i];
    ctx[i] = s;
}

// ---------------- attn out: o[e,t] = sum_d ctx[d,e] * softmax_d(q[:,t]) * scale ----------------
__global__ void attn_out_kernel(const float* __restrict__ q, size_t strideB, int qoff,
                                const float* __restrict__ ctx,
                                float* __restrict__ o, size_t oStrideB)
{
    int bh = blockIdx.x;
    int b = bh / NH, h = bh % NH;
    int t = blockIdx.y * 256 + threadIdx.x;
    __shared__ float cs[32][32];
    for (int i = threadIdx.x; i < 1024; i += 256)
        cs[i >> 5][i & 31] = ctx[(size_t)bh*1024 + i];
    __syncthreads();
    const float* qp = q + (size_t)b*strideB + (size_t)(qoff + h*32)*TT + t;
    float p[32];
    float mx = -1e30f;
    #pragma unroll
    for (int d = 0; d < 32; d++) { p[d] = qp[(size_t)d*TT]; mx = fmaxf(mx, p[d]); }
    float s = 0.f;
    #pragma unroll
    for (int d = 0; d < 32; d++) { p[d] = expf(p[d] - mx); s += p[d]; }
    float inv = 0.17677669529663687f / s;   // (1/sqrt(32)) / sum
    #pragma unroll
    for (int d = 0; d < 32; d++) p[d] *= inv;
    float accv[32];
    #pragma unroll
    for (int e = 0; e < 32; e++) accv[e] = 0.f;
    #pragma unroll
    for (int d = 0; d < 32; d++) {
        float pd = p[d];
        #pragma unroll
        for (int e4 = 0; e4 < 8; e4++) {
            float4 cv = *(const float4*)&cs[d][e4*4];
            accv[e4*4+0] += cv.x * pd;
            accv[e4*4+1] += cv.y * pd;
            accv[e4*4+2] += cv.z * pd;
            accv[e4*4+3] += cv.w * pd;
        }
    }
    float* op = o + (size_t)b*oStrideB + (size_t)(h*32)*TT + t;
    #pragma unroll
    for (int e = 0; e < 32; e++) op[(size_t)e*TT] = accv[e];
}

// ---------------- y = gn(v)*g + b + r  (elementwise, float4) ----------------
__global__ void gn_add_kernel(const float* __restrict__ v,
                              const float* __restrict__ gamma, const float* __restrict__ beta,
                              const float* __restrict__ mu, const float* __restrict__ rs,
                              const float* __restrict__ r, float* __restrict__ y)
{
    size_t i = ((size_t)blockIdx.x * 256 + threadIdx.x) * 4;
    int c = (int)((i / TT) % DIMC);
    int b = (int)(i / ((size_t)DIMC * TT));
    int grp = c >> 3;  // GC = 8
    float rr = rs[b*32 + grp], m = mu[b*32 + grp];
    float sc = gamma[c] * rr;
    float sh = beta[c] - m * sc;
    float4 vv = *(const float4*)(v + i);
    float4 rv = *(const float4*)(r + i);
    float4 o;
    o.x = vv.x * sc + sh + rv.x;
    o.y = vv.y * sc + sh + rv.y;
    o.z = vv.z * sc + sh + rv.z;
    o.w = vv.w * sc + sh + rv.w;
    *(float4*)(y + i) = o;
}

// ---------------- host orchestration ----------------
extern "C" void kernel_launch(void* const* d_in, const int* in_sizes, int n_in,
                              void* d_out, int out_size)
{
    const float* x     = (const float*)d_in[0];
    const float* c     = (const float*)d_in[1];
    const float* W_qkv = (const float*)d_in[2];
    const float* W_so  = (const float*)d_in[3];
    const float* b_so  = (const float*)d_in[4];
    const float* sa_g  = (const float*)d_in[5];
    const float* sa_b  = (const float*)d_in[6];
    const float* W_cq  = (const float*)d_in[7];
    const float* W_ckv = (const float*)d_in[8];
    const float* W_co  = (const float*)d_in[9];
    const float* b_co  = (const float*)d_in[10];
    const float* ca_g  = (const float*)d_in[11];
    const float* ca_b  = (const float*)d_in[12];
    const float* W_m1  = (const float*)d_in[13];
    const float* b_m1  = (const float*)d_in[14];
    const float* W_m2  = (const float*)d_in[15];
    const float* b_m2  = (const float*)d_in[16];
    const float* nm_g  = (const float*)d_in[17];
    const float* nm_b  = (const float*)d_in[18];
    const float* nm1_g = (const float*)d_in[19];
    const float* nm1_b = (const float*)d_in[20];
    const float* nm2_g = (const float*)d_in[21];
    const float* nm2_b = (const float*)d_in[22];
    const float* nm3_g = (const float*)d_in[23];
    const float* nm3_b = (const float*)d_in[24];
    float* out = (float*)d_out;

    float *big, *attn, *so, *xb, *wt, *beff, *mu, *rs, *aa, *ab, *kmax, *kinv, *ctx, *ctxp;
    cudaGetSymbolAddress((void**)&big,  g_big);
    cudaGetSymbolAddress((void**)&attn, g_attn);
    cudaGetSymbolAddress((void**)&so,   g_so);
    cudaGetSymbolAddress((void**)&xb,   g_x);
    cudaGetSymbolAddress((void**)&wt,   g_wt);
    cudaGetSymbolAddress((void**)&beff, g_beff);
    cudaGetSymbolAddress((void**)&mu,   g_mu);
    cudaGetSymbolAddress((void**)&rs,   g_rs);
    cudaGetSymbolAddress((void**)&aa,   g_affa);
    cudaGetSymbolAddress((void**)&ab,   g_affb);
    cudaGetSymbolAddress((void**)&kmax, g_kmax);
    cudaGetSymbolAddress((void**)&kinv, g_kinv);
    cudaGetSymbolAddress((void**)&ctx,  g_ctx);
    cudaGetSymbolAddress((void**)&ctxp, g_ctxp);

    const dim3 tb8(32, 8);
    const size_t XT = (size_t)DIMC * TT;   // 256*T

    // ================= Phase 1: self linear attention =================
    gn_stats_kernel<<<BQ*32, 256>>>(x, 8, mu, rs);
    affine_kernel<<<BQ, 256>>>(nm_g, nm_b, mu, rs, aa, ab, 256);
    foldT_kernel<<<dim3(8, 24, BQ), tb8>>>(W_qkv, aa, wt, 768, 256);
    beff_kernel<<<dim3(768, BQ), 128>>>(W_qkv, ab, nullptr, beff, 768, 256);
    gemm_kernel<<<dim3(64, 6, BQ), 256>>>(wt, (size_t)768*256, beff, 768,
                                          x, XT, big, (size_t)768*TT,
                                          nullptr, 0, 768, 256, 0);
    ksm_stats_kernel<<<dim3(256, BQ), 256>>>(big + (size_t)256*TT, (size_t)768*TT, kmax, kinv);
    ctx_kernel<<<dim3(64, 8), 256>>>(big, (size_t)768*TT, 256, 512, kmax, kinv, ctxp);
    ctx_reduce_kernel<<<256, 256>>>(ctxp, ctx);
    attn_out_kernel<<<dim3(64, 32), 256>>>(big, (size_t)768*TT, 0, ctx, attn, XT);
    foldT_kernel<<<dim3(8, 8, 1), tb8>>>(W_so, nullptr, wt, 256, 256);
    gemm_kernel<<<dim3(64, 2, BQ), 256>>>(wt, 0, b_so, 0,
                                          attn, XT, so, XT,
                                          nullptr, 0, 256, 256, 0);
    gn_stats_kernel<<<BQ*32, 256>>>(so, 8, mu, rs);
    gn_add_kernel<<<16384, 256>>>(so, sa_g, sa_b, mu, rs, x, xb);

    // ================= Phase 2: cross linear attention =================
    gn_stats_kernel<<<BQ*32, 256>>>(xb, 8, mu, rs);
    affine_kernel<<<BQ, 256>>>(nm1_g, nm1_b, mu, rs, aa, ab, 256);
    foldT_kernel<<<dim3(8, 8, BQ), tb8>>>(W_cq, aa, wt, 256, 256);
    beff_kernel<<<dim3(256, BQ), 128>>>(W_cq, ab, nullptr, beff, 256, 256);
    gemm_kernel<<<dim3(64, 2, BQ), 256>>>(wt, (size_t)256*256, beff, 256,
                                          xb, XT, attn, XT,
                                          nullptr, 0, 256, 256, 0);
    gn_stats_kernel<<<BQ*32, 256>>>(c, 16, mu, rs);
    affine_kernel<<<BQ, 256>>>(nm3_g, nm3_b, mu, rs, aa, ab, 512);
    foldT_kernel<<<dim3(16, 16, BQ), tb8>>>(W_ckv, aa, wt, 512, 512);
    beff_kernel<<<dim3(512, BQ), 128>>>(W_ckv, ab, nullptr, beff, 512, 512);
    gemm_kernel<<<dim3(64, 4, BQ), 256>>>(wt, (size_t)512*512, beff, 512,
                                          c, (size_t)512*TT, big, (size_t)512*TT,
                                          nullptr, 0, 512, 512, 0);
    ksm_stats_kernel<<<dim3(256, BQ), 256>>>(big, (size_t)512*TT, kmax, kinv);
    ctx_kernel<<<dim3(64, 8), 256>>>(big, (size_t)512*TT, 0, 256, kmax, kinv, ctxp);
    ctx_reduce_kernel<<<256, 256>>>(ctxp, ctx);
    attn_out_kernel<<<dim3(64, 32), 256>>>(attn, XT, 0, ctx, big, XT);
    foldT_kernel<<<dim3(8, 8, 1), tb8>>>(W_co, nullptr, wt, 256, 256);
    gemm_kernel<<<dim3(64, 2, BQ), 256>>>(wt, 0, b_co, 0,
                                          big, XT, so, XT,
                                          nullptr, 0, 256, 256, 0);
    gn_stats_kernel<<<BQ*32, 256>>>(so, 8, mu, rs);
    gn_add_kernel<<<16384, 256>>>(so, ca_g, ca_b, mu, rs, xb, xb);

    // ================= Phase 3: SiLU MLP =================
    gn_stats_kernel<<<BQ*32, 256>>>(xb, 8, mu, rs);
    affine_kernel<<<BQ, 256>>>(nm2_g, nm2_b, mu, rs, aa, ab, 256);
    foldT_kernel<<<dim3(8, 20, BQ), tb8>>>(W_m1, aa, wt, 640, 256);
    beff_kernel<<<dim3(640, BQ), 128>>>(W_m1, ab, b_m1, beff, 640, 256);
    gemm_kernel<<<dim3(64, 5, BQ), 256>>>(wt, (size_t)640*256, beff, 640,
                                          xb, XT, big, (size_t)640*TT,
                                          nullptr, 0, 640, 256, 1 /*silu*/);
    foldT_kernel<<<dim3(20, 8, 1), tb8>>>(W_m2, nullptr, wt, 256, 640);
    gemm_kernel<<<dim3(64, 2, BQ), 256>>>(wt, 0, b_m2, 0,
                                          big, (size_t)640*TT, out, XT,
                                          xb, XT, 256, 640, 2 /*residual*/);
}